// round 4
// baseline (speedup 1.0000x reference)
#include <cuda_runtime.h>

// Problem shapes (fixed by the dataset)
#define Bb   8
#define Tt   64
#define Nn   256
#define Dd   128
#define MTOK (Bb*Tt*Nn)     // 131072 tokens
#define K2   256            // 2*D (concat input dim)
#define QKVN 384            // 3*D output cols of fused QKV GEMM

// Scratch (device globals; no allocation allowed)
__device__ float g_Wqkv[K2*QKVN];   // packed [256][384] = Wq|Wk|Wv
__device__ float g_bqkv[QKVN];
__device__ float g_Q[MTOK*Dd];
__device__ float g_K[MTOK*Dd];
__device__ float g_V[MTOK*Dd];
__device__ float g_AO[MTOK*Dd];

// ---------------------------------------------------------------------------
// Kernel 0: pack Wq/Wk/Wv ([256,128] each, row-major) into g_Wqkv [256,384]
// ---------------------------------------------------------------------------
__global__ void pack_w(const float* __restrict__ Wq, const float* __restrict__ bq,
                       const float* __restrict__ Wk, const float* __restrict__ bk,
                       const float* __restrict__ Wv, const float* __restrict__ bv) {
    int i = blockIdx.x * blockDim.x + threadIdx.x;   // over K2*Dd = 32768
    if (i < K2 * Dd) {
        int k = i / Dd, j = i % Dd;
        g_Wqkv[k*QKVN + j        ] = Wq[i];
        g_Wqkv[k*QKVN + Dd   + j ] = Wk[i];
        g_Wqkv[k*QKVN + 2*Dd + j ] = Wv[i];
    }
    if (i < Dd) {
        g_bqkv[i]        = bq[i];
        g_bqkv[Dd + i]   = bk[i];
        g_bqkv[2*Dd + i] = bv[i];
    }
}

// ---------------------------------------------------------------------------
// Kernel 1: QKV GEMM.  C[M=131072, 384] = relu( [X|STE] @ Wqkv + b )
// 128x128 tile, BK=8, 256 threads, 8x8 micro-tile, float4 I/O,
// double-buffered smem (1 sync per k-iteration).
// Each 128-col tile maps entirely to one of Q/K/V.
// ---------------------------------------------------------------------------
__global__ __launch_bounds__(256) void qkv_gemm(const float* __restrict__ X,
                                                const float* __restrict__ STE) {
    __shared__ float As[2][8][128];   // As[buf][k][m]
    __shared__ float Bs[2][8][128];   // Bs[buf][k][j]

    const int tid = threadIdx.x;
    const int tx = tid & 15;        // col group (0..15)
    const int ty = tid >> 4;        // row group (0..15)
    const int m0 = blockIdx.x * 128;
    const int j0 = blockIdx.y * 128;

    float acc[8][8];
    #pragma unroll
    for (int i = 0; i < 8; i++)
        #pragma unroll
        for (int j = 0; j < 8; j++) acc[i][j] = 0.f;

    // A-tile load coords: one float4 per thread
    const int am = tid >> 1;            // row within tile (0..127)
    const int ak = (tid & 1) * 4;       // k offset (0 or 4)
    // B-tile load coords: one float4 per thread
    const int bk = tid >> 5;            // k (0..7)
    const int bj = (tid & 31) * 4;      // col (0..124)

    const int NIT = K2 / 8;             // 32

    // Preload tile 0 into buffer 0
    {
        float4 av = *(const float4*)&X[(size_t)(m0 + am) * Dd + ak];
        As[0][ak + 0][am] = av.x;
        As[0][ak + 1][am] = av.y;
        As[0][ak + 2][am] = av.z;
        As[0][ak + 3][am] = av.w;
        float4 bv4 = *(const float4*)&g_Wqkv[(size_t)bk * QKVN + j0 + bj];
        *(float4*)&Bs[0][bk][bj] = bv4;
    }
    __syncthreads();

    for (int it = 0; it < NIT; it++) {
        const int cur = it & 1;
        const int nxt = cur ^ 1;

        float4 av, bv4;
        const bool has_next = (it + 1 < NIT);
        if (has_next) {
            int k0 = (it + 1) * 8;
            const float* src = (k0 < Dd) ? X : STE;
            int gk = (k0 & (Dd - 1)) + ak;
            av  = *(const float4*)&src[(size_t)(m0 + am) * Dd + gk];
            bv4 = *(const float4*)&g_Wqkv[(size_t)(k0 + bk) * QKVN + j0 + bj];
        }

        #pragma unroll
        for (int k = 0; k < 8; k++) {
            float4 a0 = *(const float4*)&As[cur][k][ty * 8];
            float4 a1 = *(const float4*)&As[cur][k][ty * 8 + 4];
            float4 b0 = *(const float4*)&Bs[cur][k][tx * 8];
            float4 b1 = *(const float4*)&Bs[cur][k][tx * 8 + 4];
            float a[8] = {a0.x,a0.y,a0.z,a0.w,a1.x,a1.y,a1.z,a1.w};
            float b[8] = {b0.x,b0.y,b0.z,b0.w,b1.x,b1.y,b1.z,b1.w};
            #pragma unroll
            for (int i = 0; i < 8; i++)
                #pragma unroll
                for (int j = 0; j < 8; j++) acc[i][j] = fmaf(a[i], b[j], acc[i][j]);
        }

        if (has_next) {
            As[nxt][ak + 0][am] = av.x;
            As[nxt][ak + 1][am] = av.y;
            As[nxt][ak + 2][am] = av.z;
            As[nxt][ak + 3][am] = av.w;
            *(float4*)&Bs[nxt][bk][bj] = bv4;
        }
        __syncthreads();
    }

    // Epilogue: bias + relu; whole tile goes to exactly one of Q/K/V
    float* dst = (j0 == 0) ? g_Q : ((j0 == Dd) ? g_K : g_V);
    #pragma unroll
    for (int i = 0; i < 8; i++) {
        int m = m0 + ty * 8 + i;
        #pragma unroll
        for (int jq = 0; jq < 8; jq += 4) {
            int jl = tx * 8 + jq;           // 0..127 within tile
            float4 r;
            r.x = fmaxf(acc[i][jq+0] + g_bqkv[j0 + jl + 0], 0.f);
            r.y = fmaxf(acc[i][jq+1] + g_bqkv[j0 + jl + 1], 0.f);
            r.z = fmaxf(acc[i][jq+2] + g_bqkv[j0 + jl + 2], 0.f);
            r.w = fmaxf(acc[i][jq+3] + g_bqkv[j0 + jl + 3], 0.f);
            *(float4*)&dst[(size_t)m * Dd + jl] = r;
        }
    }
}

// ---------------------------------------------------------------------------
// Kernel 2: causal attention. 2 instances per 128-thread block.
// 32768 instances total; each: T=64 rows, head_dim=8, scale 0.25.
// Thread t (0..63 within instance) owns query row t.
// ---------------------------------------------------------------------------
__global__ __launch_bounds__(128) void attn_kernel() {
    __shared__ float sK[2][64][9];   // padded rows vs bank conflicts
    __shared__ float sV[2][64][9];
    __shared__ float sS[2][64][65];  // scores, padded

    const int li   = threadIdx.x >> 6;            // instance slot in block (0/1)
    const int inst = blockIdx.x * 2 + li;
    const int b = inst >> 12;          // / (Nn*16)
    const int r = inst & 4095;
    const int n = r >> 4;
    const int c = r & 15;
    const int t = threadIdx.x & 63;    // 0..63

    const size_t base = ((((size_t)b * Tt + t) * Nn + n) * Dd) + (size_t)c * 8;

    float q[8];
    {
        float4 k0 = *(const float4*)&g_K[base];
        float4 k1 = *(const float4*)&g_K[base + 4];
        float4 v0 = *(const float4*)&g_V[base];
        float4 v1 = *(const float4*)&g_V[base + 4];
        float4 q0 = *(const float4*)&g_Q[base];
        float4 q1 = *(const float4*)&g_Q[base + 4];
        sK[li][t][0]=k0.x; sK[li][t][1]=k0.y; sK[li][t][2]=k0.z; sK[li][t][3]=k0.w;
        sK[li][t][4]=k1.x; sK[li][t][5]=k1.y; sK[li][t][6]=k1.z; sK[li][t][7]=k1.w;
        sV[li][t][0]=v0.x; sV[li][t][1]=v0.y; sV[li][t][2]=v0.z; sV[li][t][3]=v0.w;
        sV[li][t][4]=v1.x; sV[li][t][5]=v1.y; sV[li][t][6]=v1.z; sV[li][t][7]=v1.w;
        q[0]=q0.x; q[1]=q0.y; q[2]=q0.z; q[3]=q0.w;
        q[4]=q1.x; q[5]=q1.y; q[6]=q1.z; q[7]=q1.w;
    }
    __syncthreads();

    // pass 1: scores + row max (causal: s <= t)
    float mx = -1e30f;
    for (int s = 0; s <= t; s++) {
        float d = 0.f;
        #pragma unroll
        for (int h = 0; h < 8; h++) d = fmaf(q[h], sK[li][s][h], d);
        d *= 0.25f;
        sS[li][t][s] = d;
        mx = fmaxf(mx, d);
    }
    // pass 2: softmax-weighted V accumulate
    float denom = 0.f;
    float acc[8];
    #pragma unroll
    for (int h = 0; h < 8; h++) acc[h] = 0.f;
    for (int s = 0; s <= t; s++) {
        float p = __expf(sS[li][t][s] - mx);
        denom += p;
        #pragma unroll
        for (int h = 0; h < 8; h++) acc[h] = fmaf(p, sV[li][s][h], acc[h]);
    }
    float inv = 1.f / denom;
    float4 o0 = make_float4(acc[0]*inv, acc[1]*inv, acc[2]*inv, acc[3]*inv);
    float4 o1 = make_float4(acc[4]*inv, acc[5]*inv, acc[6]*inv, acc[7]*inv);
    *(float4*)&g_AO[base]     = o0;
    *(float4*)&g_AO[base + 4] = o1;
}

// ---------------------------------------------------------------------------
// Kernel 3: output projection.  out = relu(AO @ Wo + bo), Wo [128,128]
// Same tiling as kernel 1: 128x128 tile, BK=8, 8x8 microtile, double buffer.
// ---------------------------------------------------------------------------
__global__ __launch_bounds__(256) void out_gemm(const float* __restrict__ Wo,
                                                const float* __restrict__ bo,
                                                float* __restrict__ out) {
    __shared__ float As[2][8][128];
    __shared__ float Bs[2][8][128];

    const int tid = threadIdx.x;
    const int tx = tid & 15;
    const int ty = tid >> 4;
    const int m0 = blockIdx.x * 128;

    float acc[8][8];
    #pragma unroll
    for (int i = 0; i < 8; i++)
        #pragma unroll
        for (int j = 0; j < 8; j++) acc[i][j] = 0.f;

    const int am = tid >> 1;
    const int ak = (tid & 1) * 4;
    const int bk = tid >> 5;
    const int bj = (tid & 31) * 4;

    const int NIT = Dd / 8;             // 16

    {
        float4 av = *(const float4*)&g_AO[(size_t)(m0 + am) * Dd + ak];
        As[0][ak + 0][am] = av.x;
        As[0][ak + 1][am] = av.y;
        As[0][ak + 2][am] = av.z;
        As[0][ak + 3][am] = av.w;
        float4 bv4 = *(const float4*)&Wo[(size_t)bk * Dd + bj];
        *(float4*)&Bs[0][bk][bj] = bv4;
    }
    __syncthreads();

    for (int it = 0; it < NIT; it++) {
        const int cur = it & 1;
        const int nxt = cur ^ 1;

        float4 av, bv4;
        const bool has_next = (it + 1 < NIT);
        if (has_next) {
            int k0 = (it + 1) * 8;
            av  = *(const float4*)&g_AO[(size_t)(m0 + am) * Dd + k0 + ak];
            bv4 = *(const float4*)&Wo[(size_t)(k0 + bk) * Dd + bj];
        }

        #pragma unroll
        for (int k = 0; k < 8; k++) {
            float4 a0 = *(const float4*)&As[cur][k][ty * 8];
            float4 a1 = *(const float4*)&As[cur][k][ty * 8 + 4];
            float4 b0 = *(const float4*)&Bs[cur][k][tx * 8];
            float4 b1 = *(const float4*)&Bs[cur][k][tx * 8 + 4];
            float a[8] = {a0.x,a0.y,a0.z,a0.w,a1.x,a1.y,a1.z,a1.w};
            float b[8] = {b0.x,b0.y,b0.z,b0.w,b1.x,b1.y,b1.z,b1.w};
            #pragma unroll
            for (int i = 0; i < 8; i++)
                #pragma unroll
                for (int j = 0; j < 8; j++) acc[i][j] = fmaf(a[i], b[j], acc[i][j]);
        }

        if (has_next) {
            As[nxt][ak + 0][am] = av.x;
            As[nxt][ak + 1][am] = av.y;
            As[nxt][ak + 2][am] = av.z;
            As[nxt][ak + 3][am] = av.w;
            *(float4*)&Bs[nxt][bk][bj] = bv4;
        }
        __syncthreads();
    }

    #pragma unroll
    for (int i = 0; i < 8; i++) {
        int m = m0 + ty * 8 + i;
        #pragma unroll
        for (int jq = 0; jq < 8; jq += 4) {
            int jl = tx * 8 + jq;
            float4 r;
            r.x = fmaxf(acc[i][jq+0] + bo[jl + 0], 0.f);
            r.y = fmaxf(acc[i][jq+1] + bo[jl + 1], 0.f);
            r.z = fmaxf(acc[i][jq+2] + bo[jl + 2], 0.f);
            r.w = fmaxf(acc[i][jq+3] + bo[jl + 3], 0.f);
            *(float4*)&out[(size_t)m * Dd + jl] = r;
        }
    }
}

// ---------------------------------------------------------------------------
extern "C" void kernel_launch(void* const* d_in, const int* in_sizes, int n_in,
                              void* d_out, int out_size) {
    const float* X   = (const float*)d_in[0];
    const float* STE = (const float*)d_in[1];
    const float* Wq  = (const float*)d_in[2];
    const float* bq  = (const float*)d_in[3];
    const float* Wk  = (const float*)d_in[4];
    const float* bk  = (const float*)d_in[5];
    const float* Wv  = (const float*)d_in[6];
    const float* bv  = (const float*)d_in[7];
    const float* Wo  = (const float*)d_in[8];
    const float* bo  = (const float*)d_in[9];
    float* out = (float*)d_out;

    pack_w<<<128, 256>>>(Wq, bq, Wk, bk, Wv, bv);

    dim3 gA(MTOK / 128, QKVN / 128);      // 1024 x 3
    qkv_gemm<<<gA, 256>>>(X, STE);

    attn_kernel<<<Bb * Nn * 8, 128>>>();  // 32768 instances, 2 per block

    dim3 gC(MTOK / 128, 1);               // 1024
    out_gemm<<<gC, 256>>>(Wo, bo, out);
}

// round 9
// speedup vs baseline: 1.2827x; 1.2827x over previous
#include <cuda_runtime.h>
#include <cstdint>

// Problem shapes (fixed by the dataset)
#define Bb   8
#define Tt   64
#define Nn   256
#define Dd   128
#define MTOK (Bb*Tt*Nn)     // 131072 tokens
#define K2   256            // 2*D (concat input dim)
#define QKVN 384            // 3*D output cols of fused QKV GEMM

#define SPAD 136            // smem row stride in words ([k][m] layout)

// Scratch (device globals; no allocation allowed)
__device__ float g_Wqkv[K2*QKVN];   // packed [256][384] = Wq|Wk|Wv
__device__ float g_bqkv[QKVN];
__device__ float g_Q[MTOK*Dd];
__device__ float g_K[MTOK*Dd];
__device__ float g_V[MTOK*Dd];
__device__ float g_AO[MTOK*Dd];

// ---------------------------------------------------------------------------
__device__ __forceinline__ uint32_t f2tf32(float x) {
    uint32_t r;
    asm("cvt.rna.tf32.f32 %0, %1;" : "=r"(r) : "f"(x));
    return r;
}

__device__ __forceinline__ void mma8(float* c, const uint32_t* a, const uint32_t* b) {
    asm volatile(
        "mma.sync.aligned.m16n8k8.row.col.f32.tf32.tf32.f32 "
        "{%0,%1,%2,%3}, {%4,%5,%6,%7}, {%8,%9}, {%0,%1,%2,%3};"
        : "+f"(c[0]), "+f"(c[1]), "+f"(c[2]), "+f"(c[3])
        : "r"(a[0]), "r"(a[1]), "r"(a[2]), "r"(a[3]),
          "r"(b[0]), "r"(b[1]));
}

// ---------------------------------------------------------------------------
// Kernel 0: pack Wq/Wk/Wv ([256,128] each, row-major) into g_Wqkv [256,384]
// ---------------------------------------------------------------------------
__global__ void pack_w(const float* __restrict__ Wq, const float* __restrict__ bq,
                       const float* __restrict__ Wk, const float* __restrict__ bk,
                       const float* __restrict__ Wv, const float* __restrict__ bv) {
    int i = blockIdx.x * blockDim.x + threadIdx.x;
    if (i < K2 * Dd) {
        int k = i / Dd, j = i % Dd;
        g_Wqkv[k*QKVN + j        ] = Wq[i];
        g_Wqkv[k*QKVN + Dd   + j ] = Wk[i];
        g_Wqkv[k*QKVN + 2*Dd + j ] = Wv[i];
    }
    if (i < Dd) {
        g_bqkv[i]        = bq[i];
        g_bqkv[Dd + i]   = bk[i];
        g_bqkv[2*Dd + i] = bv[i];
    }
}

// ---------------------------------------------------------------------------
// 3xTF32 tensor-core GEMM core.
// BM=BN=128, BK=8, 128 threads, 4 warps (2x2), 64x64 per warp.
// Smem layout [k][x] stride SPAD; hi/lo split for 3xTF32.
// ---------------------------------------------------------------------------

struct TileRegs {
    float4 a0, a1;   // A rows ar, ar+64 (4 k each)
    float4 b0, b1;   // B row bk8, cols bn0..bn0+7
};

// store one float4 (A row 'row', k base ak4) with rotation; hi/lo
__device__ __forceinline__ void storeA4(float* sAh, float* sAl,
                                        int row, int ak4, int par, float4 v) {
    const float vv[4] = {v.x, v.y, v.z, v.w};
    #pragma unroll
    for (int ii = 0; ii < 4; ii++) {
        int q = (ii + 2*par) & 3;
        float x = vv[q];
        uint32_t h = f2tf32(x);
        float hf = __uint_as_float(h);
        uint32_t l = f2tf32(x - hf);
        sAh[(ak4+q)*SPAD + row] = hf;
        sAl[(ak4+q)*SPAD + row] = __uint_as_float(l);
    }
}

__device__ __forceinline__ void storeB8(float* sBh, float* sBl,
                                        int bk8, int bn0, int c4, float4 v0, float4 v1) {
    const float vv[8] = {v0.x,v0.y,v0.z,v0.w, v1.x,v1.y,v1.z,v1.w};
    #pragma unroll
    for (int ii = 0; ii < 8; ii++) {
        int j = (ii + 2*c4) & 7;
        float x = vv[j];
        uint32_t h = f2tf32(x);
        float hf = __uint_as_float(h);
        uint32_t l = f2tf32(x - hf);
        sBh[bk8*SPAD + bn0 + j] = hf;
        sBl[bk8*SPAD + bn0 + j] = __uint_as_float(l);
    }
}

#define GEMM_COMPUTE(sAh, sAl, sBh, sBl)                                     \
    {                                                                        \
        uint32_t Ah[4][4], Al[4][4], Bh[8][2], Bl[8][2];                     \
        _Pragma("unroll")                                                    \
        for (int im = 0; im < 4; im++) {                                     \
            int m = wm + im*16 + g;                                          \
            Ah[im][0] = __float_as_uint((sAh)[ t   *SPAD + m    ]);          \
            Ah[im][1] = __float_as_uint((sAh)[ t   *SPAD + m + 8]);          \
            Ah[im][2] = __float_as_uint((sAh)[(t+4)*SPAD + m    ]);          \
            Ah[im][3] = __float_as_uint((sAh)[(t+4)*SPAD + m + 8]);          \
            Al[im][0] = __float_as_uint((sAl)[ t   *SPAD + m    ]);          \
            Al[im][1] = __float_as_uint((sAl)[ t   *SPAD + m + 8]);          \
            Al[im][2] = __float_as_uint((sAl)[(t+4)*SPAD + m    ]);          \
            Al[im][3] = __float_as_uint((sAl)[(t+4)*SPAD + m + 8]);          \
        }                                                                    \
        _Pragma("unroll")                                                    \
        for (int in = 0; in < 8; in++) {                                     \
            int n = wn + in*8 + g;                                           \
            Bh[in][0] = __float_as_uint((sBh)[ t   *SPAD + n]);              \
            Bh[in][1] = __float_as_uint((sBh)[(t+4)*SPAD + n]);              \
            Bl[in][0] = __float_as_uint((sBl)[ t   *SPAD + n]);              \
            Bl[in][1] = __float_as_uint((sBl)[(t+4)*SPAD + n]);              \
        }                                                                    \
        _Pragma("unroll")                                                    \
        for (int im = 0; im < 4; im++)                                       \
            _Pragma("unroll")                                                \
            for (int in = 0; in < 8; in++) mma8(acc[im][in], Ah[im], Bh[in]);\
        _Pragma("unroll")                                                    \
        for (int im = 0; im < 4; im++)                                       \
            _Pragma("unroll")                                                \
            for (int in = 0; in < 8; in++) mma8(acc[im][in], Al[im], Bh[in]);\
        _Pragma("unroll")                                                    \
        for (int im = 0; im < 4; im++)                                       \
            _Pragma("unroll")                                                \
            for (int in = 0; in < 8; in++) mma8(acc[im][in], Ah[im], Bl[in]);\
    }

// ---------------------------------------------------------------------------
// Kernel 1: QKV GEMM (3xTF32).  relu([X|STE] @ Wqkv + b) -> g_Q/g_K/g_V
// ---------------------------------------------------------------------------
__global__ __launch_bounds__(128) void qkv_gemm_tc(const float* __restrict__ X,
                                                   const float* __restrict__ STE) {
    __shared__ float sAh[2][8*SPAD], sAl[2][8*SPAD];
    __shared__ float sBh[2][8*SPAD], sBl[2][8*SPAD];

    const int tid = threadIdx.x;
    const int lane = tid & 31;
    const int wid = tid >> 5;
    const int g = lane >> 2, t = lane & 3;
    const int wm = (wid >> 1) * 64, wn = (wid & 1) * 64;
    const int m0 = blockIdx.x * 128;
    const int j0 = blockIdx.y * 128;

    // loader coords
    const int ar  = tid >> 1;          // A row (also +64)
    const int par = tid & 1;
    const int ak4 = par * 4;
    const int bk8 = tid >> 4;          // B k row 0..7
    const int bn0 = (tid & 15) * 8;
    const int bc4 = (tid & 15) >> 2;

    float acc[4][8][4];
    #pragma unroll
    for (int im = 0; im < 4; im++)
        #pragma unroll
        for (int in = 0; in < 8; in++)
            #pragma unroll
            for (int r = 0; r < 4; r++) acc[im][in][r] = 0.f;

    const int NIT = K2 / 8;   // 32

    // preload tile 0
    TileRegs tr;
    {
        tr.a0 = *(const float4*)&X[(size_t)(m0 + ar) * Dd + ak4];
        tr.a1 = *(const float4*)&X[(size_t)(m0 + ar + 64) * Dd + ak4];
        tr.b0 = *(const float4*)&g_Wqkv[(size_t)bk8 * QKVN + j0 + bn0];
        tr.b1 = *(const float4*)&g_Wqkv[(size_t)bk8 * QKVN + j0 + bn0 + 4];
    }
    storeA4(sAh[0], sAl[0], ar,      ak4, par, tr.a0);
    storeA4(sAh[0], sAl[0], ar + 64, ak4, par, tr.a1);
    storeB8(sBh[0], sBl[0], bk8, bn0, bc4, tr.b0, tr.b1);
    __syncthreads();

    for (int it = 0; it < NIT; it++) {
        const int cur = it & 1;
        const bool has_next = (it + 1 < NIT);
        if (has_next) {
            int k0 = (it + 1) * 8;
            const float* src = (k0 < Dd) ? X : STE;
            int gk = (k0 & (Dd - 1)) + ak4;
            tr.a0 = *(const float4*)&src[(size_t)(m0 + ar) * Dd + gk];
            tr.a1 = *(const float4*)&src[(size_t)(m0 + ar + 64) * Dd + gk];
            tr.b0 = *(const float4*)&g_Wqkv[(size_t)(k0 + bk8) * QKVN + j0 + bn0];
            tr.b1 = *(const float4*)&g_Wqkv[(size_t)(k0 + bk8) * QKVN + j0 + bn0 + 4];
        }

        GEMM_COMPUTE(sAh[cur], sAl[cur], sBh[cur], sBl[cur]);

        if (has_next) {
            const int nxt = cur ^ 1;
            storeA4(sAh[nxt], sAl[nxt], ar,      ak4, par, tr.a0);
            storeA4(sAh[nxt], sAl[nxt], ar + 64, ak4, par, tr.a1);
            storeB8(sBh[nxt], sBl[nxt], bk8, bn0, bc4, tr.b0, tr.b1);
        }
        __syncthreads();
    }

    // epilogue: bias + relu; whole 128-col tile -> exactly one of Q/K/V
    float* dst = (j0 == 0) ? g_Q : ((j0 == Dd) ? g_K : g_V);
    #pragma unroll
    for (int im = 0; im < 4; im++) {
        int r0 = m0 + wm + im * 16 + g;
        #pragma unroll
        for (int in = 0; in < 8; in++) {
            int c = wn + in * 8 + 2 * t;   // local col (0..127), even
            float b0v = g_bqkv[j0 + c], b1v = g_bqkv[j0 + c + 1];
            float2 o;
            o.x = fmaxf(acc[im][in][0] + b0v, 0.f);
            o.y = fmaxf(acc[im][in][1] + b1v, 0.f);
            *(float2*)&dst[(size_t)r0 * Dd + c] = o;
            o.x = fmaxf(acc[im][in][2] + b0v, 0.f);
            o.y = fmaxf(acc[im][in][3] + b1v, 0.f);
            *(float2*)&dst[(size_t)(r0 + 8) * Dd + c] = o;
        }
    }
}

// ---------------------------------------------------------------------------
// Kernel 2: causal attention. 2 instances per 128-thread block. (fp32)
// ---------------------------------------------------------------------------
__global__ __launch_bounds__(128) void attn_kernel() {
    __shared__ float sK[2][64][9];
    __shared__ float sV[2][64][9];
    __shared__ float sS[2][64][65];

    const int li   = threadIdx.x >> 6;
    const int inst = blockIdx.x * 2 + li;
    const int b = inst >> 12;
    const int r = inst & 4095;
    const int n = r >> 4;
    const int c = r & 15;
    const int t = threadIdx.x & 63;

    const size_t base = ((((size_t)b * Tt + t) * Nn + n) * Dd) + (size_t)c * 8;

    float q[8];
    {
        float4 k0 = *(const float4*)&g_K[base];
        float4 k1 = *(const float4*)&g_K[base + 4];
        float4 v0 = *(const float4*)&g_V[base];
        float4 v1 = *(const float4*)&g_V[base + 4];
        float4 q0 = *(const float4*)&g_Q[base];
        float4 q1 = *(const float4*)&g_Q[base + 4];
        sK[li][t][0]=k0.x; sK[li][t][1]=k0.y; sK[li][t][2]=k0.z; sK[li][t][3]=k0.w;
        sK[li][t][4]=k1.x; sK[li][t][5]=k1.y; sK[li][t][6]=k1.z; sK[li][t][7]=k1.w;
        sV[li][t][0]=v0.x; sV[li][t][1]=v0.y; sV[li][t][2]=v0.z; sV[li][t][3]=v0.w;
        sV[li][t][4]=v1.x; sV[li][t][5]=v1.y; sV[li][t][6]=v1.z; sV[li][t][7]=v1.w;
        q[0]=q0.x; q[1]=q0.y; q[2]=q0.z; q[3]=q0.w;
        q[4]=q1.x; q[5]=q1.y; q[6]=q1.z; q[7]=q1.w;
    }
    __syncthreads();

    float mx = -1e30f;
    for (int s = 0; s <= t; s++) {
        float d = 0.f;
        #pragma unroll
        for (int h = 0; h < 8; h++) d = fmaf(q[h], sK[li][s][h], d);
        d *= 0.25f;
        sS[li][t][s] = d;
        mx = fmaxf(mx, d);
    }
    float denom = 0.f;
    float acc[8];
    #pragma unroll
    for (int h = 0; h < 8; h++) acc[h] = 0.f;
    for (int s = 0; s <= t; s++) {
        float p = __expf(sS[li][t][s] - mx);
        denom += p;
        #pragma unroll
        for (int h = 0; h < 8; h++) acc[h] = fmaf(p, sV[li][s][h], acc[h]);
    }
    float inv = 1.f / denom;
    float4 o0 = make_float4(acc[0]*inv, acc[1]*inv, acc[2]*inv, acc[3]*inv);
    float4 o1 = make_float4(acc[4]*inv, acc[5]*inv, acc[6]*inv, acc[7]*inv);
    *(float4*)&g_AO[base]     = o0;
    *(float4*)&g_AO[base + 4] = o1;
}

// ---------------------------------------------------------------------------
// Kernel 3: output projection (3xTF32).  out = relu(AO @ Wo + bo)
// ---------------------------------------------------------------------------
__global__ __launch_bounds__(128) void out_gemm_tc(const float* __restrict__ Wo,
                                                   const float* __restrict__ bo,
                                                   float* __restrict__ out) {
    __shared__ float sAh[2][8*SPAD], sAl[2][8*SPAD];
    __shared__ float sBh[2][8*SPAD], sBl[2][8*SPAD];

    const int tid = threadIdx.x;
    const int lane = tid & 31;
    const int wid = tid >> 5;
    const int g = lane >> 2, t = lane & 3;
    const int wm = (wid >> 1) * 64, wn = (wid & 1) * 64;
    const int m0 = blockIdx.x * 128;

    const int ar  = tid >> 1;
    const int par = tid & 1;
    const int ak4 = par * 4;
    const int bk8 = tid >> 4;
    const int bn0 = (tid & 15) * 8;
    const int bc4 = (tid & 15) >> 2;

    float acc[4][8][4];
    #pragma unroll
    for (int im = 0; im < 4; im++)
        #pragma unroll
        for (int in = 0; in < 8; in++)
            #pragma unroll
            for (int r = 0; r < 4; r++) acc[im][in][r] = 0.f;

    const int NIT = Dd / 8;   // 16

    TileRegs tr;
    tr.a0 = *(const float4*)&g_AO[(size_t)(m0 + ar) * Dd + ak4];
    tr.a1 = *(const float4*)&g_AO[(size_t)(m0 + ar + 64) * Dd + ak4];
    tr.b0 = *(const float4*)&Wo[(size_t)bk8 * Dd + bn0];
    tr.b1 = *(const float4*)&Wo[(size_t)bk8 * Dd + bn0 + 4];
    storeA4(sAh[0], sAl[0], ar,      ak4, par, tr.a0);
    storeA4(sAh[0], sAl[0], ar + 64, ak4, par, tr.a1);
    storeB8(sBh[0], sBl[0], bk8, bn0, bc4, tr.b0, tr.b1);
    __syncthreads();

    for (int it = 0; it < NIT; it++) {
        const int cur = it & 1;
        const bool has_next = (it + 1 < NIT);
        if (has_next) {
            int k0 = (it + 1) * 8;
            tr.a0 = *(const float4*)&g_AO[(size_t)(m0 + ar) * Dd + k0 + ak4];
            tr.a1 = *(const float4*)&g_AO[(size_t)(m0 + ar + 64) * Dd + k0 + ak4];
            tr.b0 = *(const float4*)&Wo[(size_t)(k0 + bk8) * Dd + bn0];
            tr.b1 = *(const float4*)&Wo[(size_t)(k0 + bk8) * Dd + bn0 + 4];
        }

        GEMM_COMPUTE(sAh[cur], sAl[cur], sBh[cur], sBl[cur]);

        if (has_next) {
            const int nxt = cur ^ 1;
            storeA4(sAh[nxt], sAl[nxt], ar,      ak4, par, tr.a0);
            storeA4(sAh[nxt], sAl[nxt], ar + 64, ak4, par, tr.a1);
            storeB8(sBh[nxt], sBl[nxt], bk8, bn0, bc4, tr.b0, tr.b1);
        }
        __syncthreads();
    }

    #pragma unroll
    for (int im = 0; im < 4; im++) {
        int r0 = m0 + wm + im * 16 + g;
        #pragma unroll
        for (int in = 0; in < 8; in++) {
            int c = wn + in * 8 + 2 * t;
            float b0v = bo[c], b1v = bo[c + 1];
            float2 o;
            o.x = fmaxf(acc[im][in][0] + b0v, 0.f);
            o.y = fmaxf(acc[im][in][1] + b1v, 0.f);
            *(float2*)&out[(size_t)r0 * Dd + c] = o;
            o.x = fmaxf(acc[im][in][2] + b0v, 0.f);
            o.y = fmaxf(acc[im][in][3] + b1v, 0.f);
            *(float2*)&out[(size_t)(r0 + 8) * Dd + c] = o;
        }
    }
}

// ---------------------------------------------------------------------------
extern "C" void kernel_launch(void* const* d_in, const int* in_sizes, int n_in,
                              void* d_out, int out_size) {
    const float* X   = (const float*)d_in[0];
    const float* STE = (const float*)d_in[1];
    const float* Wq  = (const float*)d_in[2];
    const float* bq  = (const float*)d_in[3];
    const float* Wk  = (const float*)d_in[4];
    const float* bk  = (const float*)d_in[5];
    const float* Wv  = (const float*)d_in[6];
    const float* bv  = (const float*)d_in[7];
    const float* Wo  = (const float*)d_in[8];
    const float* bo  = (const float*)d_in[9];
    float* out = (float*)d_out;

    pack_w<<<128, 256>>>(Wq, bq, Wk, bk, Wv, bv);

    dim3 gA(MTOK / 128, QKVN / 128);        // 1024 x 3
    qkv_gemm_tc<<<gA, 128>>>(X, STE);

    attn_kernel<<<Bb * Nn * 8, 128>>>();    // 32768 instances, 2 per block

    out_gemm_tc<<<MTOK / 128, 128>>>(Wo, bo, out);
}